// round 1
// baseline (speedup 1.0000x reference)
#include <cuda_runtime.h>

// harmolearn: 1024-channel LIF scan over 16368 steps.
// out[c, t<16368] = spike(t), out[c, t>=16368] = inp[c, t].
//
// Key identity: mean(B,axis=0)[j] at step t == colmean[t+j] (step-independent),
// so B_ram[c](t) = sliding 16-window sum of p[c,k] = x_pad[c,k]*colmean[k].

#define CHN    1024
#define TLEN   16384
#define PADW   8
#define TP     (TLEN + 2 * PADW)   // 16400 padded columns
#define NSTEPS (TLEN - 16)         // 16368

__device__ float g_cm[TP];

// ---------------------------------------------------------------------------
// Kernel A: per-column channel mean, accumulated SEQUENTIALLY over c (ascending)
// to mirror the reference reduce order. Coalesced across threads (threads = t).
// ---------------------------------------------------------------------------
__global__ void colmean_kernel(const float* __restrict__ inp) {
    int tp = blockIdx.x * blockDim.x + threadIdx.x;
    if (tp >= TP) return;
    float m = 0.0f;
    if (tp >= PADW && tp < TLEN + PADW) {
        const float* col = inp + (tp - PADW);
        float s = 0.0f;
#pragma unroll 8
        for (int c = 0; c < CHN; ++c) {
            s = __fadd_rn(s, col[(size_t)c * TLEN]);  // strict sequential order
        }
        m = s * (1.0f / CHN);  // /1024 is exact (power of two)
    }
    g_cm[tp] = m;
}

// ---------------------------------------------------------------------------
// Kernel B: per-channel sequential scan. One thread per channel.
// 16-step unrolled tiles; window dot via suffix(pa) + prefix(pb).
// ---------------------------------------------------------------------------
__global__ void __launch_bounds__(32) scan_kernel(const float* __restrict__ inp,
                                                  float* __restrict__ out) {
    const int c = blockIdx.x * 32 + threadIdx.x;     // 32 blocks x 32 threads = 1024
    const float* row = inp + (size_t)c * TLEN;
    float* orow      = out + (size_t)c * TLEN;

    float w = 1.0f, mem = 0.0f, r = 0.0f;            // r = (mem_entering_step > 1)

    // xa/pa hold padded cols [t0, t0+16), xb/pb hold [t0+16, t0+32)
    float xa[16], pa[16], xb[16], pb[16];
#pragma unroll
    for (int j = 0; j < 16; ++j) {
        float x0 = (j >= PADW) ? row[j - PADW] : 0.0f;   // left zero-pad
        xa[j] = x0;
        pa[j] = x0 * __ldg(&g_cm[j]);
        float x1 = row[16 + j - PADW];
        xb[j] = x1;
        pb[j] = x1 * __ldg(&g_cm[16 + j]);
    }

    for (int t0 = 0; t0 < NSTEPS; t0 += 16) {
        // suffix sums of pa: suf[i] = pa[i] + ... + pa[15]
        float suf[16];
        suf[15] = pa[15];
#pragma unroll
        for (int i = 14; i >= 0; --i) suf[i] = __fadd_rn(pa[i], suf[i + 1]);

        float pre = 0.0f;           // prefix over pb
        float4 sv;
#pragma unroll
        for (int i = 0; i < 16; ++i) {
            // window dot: d = sum_{k=t0+i}^{t0+i+15} p[k]
            float d = (i == 0) ? suf[0] : __fadd_rn(suf[i], pre);

            // w = clip(0.5*w + 0.5*d, -1, 3)  (x0.5 exact -> contraction-safe)
            w = fminf(fmaxf(__fmaf_rn(0.5f, w, 0.5f * d), -1.0f), 3.0f);

            // mem = 0.95*mem + w*x - reset   (non-contracted, mul/mul/add/sub)
            float bm = __fmul_rn(0.95f, mem);
            float wx = __fmul_rn(w, xa[i]);
            mem = __fsub_rn(__fadd_rn(bm, wx), r);

            // spike now == reset for the next step
            r = (mem > 1.0f) ? 1.0f : 0.0f;
            ((float*)&sv)[i & 3] = r;
            if ((i & 3) == 3) {
                *reinterpret_cast<float4*>(orow + t0 + i - 3) = sv;
            }
            pre = __fadd_rn(pre, pb[i]);
        }

        // rotate window and fetch next 16 padded columns [t0+32, t0+48)
#pragma unroll
        for (int j = 0; j < 16; ++j) { xa[j] = xb[j]; pa[j] = pb[j]; }
        const int base = t0 + 32;
#pragma unroll
        for (int j = 0; j < 16; ++j) {
            int k = base + j;                          // k <= 16399 < TP
            float x = (k < TLEN + PADW) ? row[k - PADW] : 0.0f;
            xb[j] = x;
            pb[j] = x * __ldg(&g_cm[k]);
        }
    }

    // tail: out[:, 16368:16384] = inp[:, 16368:16384]
#pragma unroll
    for (int t = NSTEPS; t < TLEN; ++t) orow[t] = row[t];
}

extern "C" void kernel_launch(void* const* d_in, const int* in_sizes, int n_in,
                              void* d_out, int out_size) {
    const float* inp = (const float*)d_in[0];
    float* out = (float*)d_out;
    (void)in_sizes; (void)n_in; (void)out_size;

    colmean_kernel<<<(TP + 255) / 256, 256>>>(inp);
    scan_kernel<<<CHN / 32, 32>>>(inp, out);
}

// round 2
// speedup vs baseline: 6.5303x; 6.5303x over previous
#include <cuda_runtime.h>

// harmolearn: 1024-channel LIF scan over 16368 steps, parallelized over time
// via contraction warm-up chunks.
//
// Identity: mean(B,axis=0)[j] at step t == colmean[t+j], so
// B_ram[c](t) = 16-window sliding sum of p[c,k] = x_pad[c,k]*colmean[k].
// w decays x0.5/step, mem x0.95/step -> state bit-converges within ~400 steps,
// so chunks of 528 steps with 512-step warm-up reproduce the exact trajectory.

#define CHN    1024
#define TLEN   16384
#define PADW   8
#define TP     (TLEN + 2 * PADW)   // 16400
#define NSTEPS (TLEN - 16)         // 16368
#define NCHUNK 31
#define BODY   528                 // 33 tiles of 16;  31*528 = 16368
#define WARM   512                 // 32 tiles
#define BTILES (BODY / 16)         // 33
#define WTILES (WARM / 16)         // 32

__device__ float g_cm[TP];

// ---------------------------------------------------------------------------
// Kernel A: per-column channel mean, strict ascending-c order (bit-exact vs
// reference; rel_err was 0.0 with this order). Coalesced across threads.
// ---------------------------------------------------------------------------
__global__ void colmean_kernel(const float* __restrict__ inp) {
    int tp = blockIdx.x * blockDim.x + threadIdx.x;
    if (tp >= TP) return;
    float m = 0.0f;
    if (tp >= PADW && tp < TLEN + PADW) {
        const float* col = inp + (tp - PADW);
        float s = 0.0f;
#pragma unroll 8
        for (int c = 0; c < CHN; ++c) {
            s = __fadd_rn(s, col[(size_t)c * TLEN]);
        }
        m = s * (1.0f / CHN);
    }
    g_cm[tp] = m;
}

// ---------------------------------------------------------------------------
// Kernel B: chunked scan. One warp per block; block = 32 consecutive channels,
// one time-chunk. Grid = 31 chunks * 32 channel-groups = 992 blocks.
// x staged through smem (coalesced, triple-buffered); spikes staged through
// smem and flushed coalesced along t.
// ---------------------------------------------------------------------------
__global__ void __launch_bounds__(32) scan_kernel(const float* __restrict__ inp,
                                                  float* __restrict__ out) {
    __shared__ float sx[3][16][33];   // x_pad staging tiles
    __shared__ float sb[16][33];      // spike staging

    const int chunk = blockIdx.x >> 5;          // 0..30
    const int c0    = (blockIdx.x & 31) << 5;   // channel group base
    const int lane  = threadIdx.x;
    const int c     = c0 + lane;
    const float* row = inp + (size_t)c * TLEN;

    const int tb        = chunk * BODY;                         // body start
    const int tw        = (chunk == 0) ? 0 : (tb - WARM);       // walk start
    const int nt        = (chunk == 0) ? BTILES : (BTILES + WTILES); // 33 / 65
    const int storeFrom = (chunk == 0) ? 0 : WTILES;

    const int tt   = lane & 15;      // t-index for staging roles
    const int half = lane >> 4;      // channel-pair selector

    float w = 1.0f, mem = 0.0f, r = 0.0f;

    // ---- prologue: register windows for tiles 0 and 1 (one-time scattered) ----
    float xa[16], pa[16], xb[16], pb[16];
#pragma unroll
    for (int j = 0; j < 16; ++j) {
        int k0 = tw + j;
        float x0 = (k0 >= PADW) ? __ldg(row + (k0 - PADW)) : 0.0f;
        xa[j] = x0;
        pa[j] = x0 * __ldg(&g_cm[k0]);
        int k1 = tw + 16 + j;
        float x1 = __ldg(row + (k1 - PADW));
        xb[j] = x1;
        pb[j] = x1 * __ldg(&g_cm[k1]);
    }

    // ---- prefill smem x buffers 0 and 1 (consumed at tiles 0 and 1) ----
    // buffer for tile k holds x_pad[tw+16k+32 .. tw+16k+48)  (= inp idx base tw+16k+24)
#pragma unroll
    for (int b = 0; b < 2; ++b) {
        int gb = tw + 16 * b + 24;                 // inp index base
#pragma unroll
        for (int g = 0; g < 16; ++g) {
            int cc = 2 * g + half;
            int idx = gb + tt;
            float v = (idx < TLEN) ? __ldg(inp + (size_t)(c0 + cc) * TLEN + idx) : 0.0f;
            sx[b][tt][cc] = v;
        }
    }
    __syncwarp();

    // ---- main loop over 16-step tiles ----
    for (int k = 0; k < nt; ++k) {
        // suffix sums of pa (right-associated, matches known-exact kernel)
        float suf[16];
        suf[15] = pa[15];
#pragma unroll
        for (int i = 14; i >= 0; --i) suf[i] = __fadd_rn(pa[i], suf[i + 1]);

        float pre = 0.0f;
#pragma unroll
        for (int i = 0; i < 16; ++i) {
            float d = (i == 0) ? suf[0] : __fadd_rn(suf[i], pre);
            w = fminf(fmaxf(__fmaf_rn(0.5f, w, 0.5f * d), -1.0f), 3.0f);
            float bm = __fmul_rn(0.95f, mem);
            float wx = __fmul_rn(w, xa[i]);
            mem = __fsub_rn(__fadd_rn(bm, wx), r);
            r = (mem > 1.0f) ? 1.0f : 0.0f;
            sb[i][lane] = r;
            pre = __fadd_rn(pre, pb[i]);
        }
        __syncwarp();

        // ---- phase 2: flush spikes, rotate window, refill staging ----
        if (k >= storeFrom) {
            int t0 = tw + 16 * k;
#pragma unroll
            for (int g = 0; g < 16; ++g) {
                int cc = 2 * g + half;
                out[(size_t)(c0 + cc) * TLEN + t0 + tt] = sb[tt][cc];
            }
        }

        if (k < nt - 1) {
            // rotate register windows
#pragma unroll
            for (int j = 0; j < 16; ++j) { xa[j] = xb[j]; pa[j] = pb[j]; }

            // consume staged x for next tile's second window: buffer k%3
            int bc = k % 3;
            int t1 = tw + 16 * k + 32;
#pragma unroll
            for (int j = 0; j < 16; ++j) {
                float x = sx[bc][j][lane];
                xb[j] = x;
                pb[j] = x * __ldg(&g_cm[t1 + j]);
            }

            // refill buffer (k+2)%3 for tile k+2: x_pad[tw+16k+64..+80)
            int br = (k + 2) % 3;
            int gb = tw + 16 * k + 56;             // inp index base
#pragma unroll
            for (int g = 0; g < 16; ++g) {
                int cc = 2 * g + half;
                int idx = gb + tt;
                float v = (idx < TLEN) ? __ldg(inp + (size_t)(c0 + cc) * TLEN + idx) : 0.0f;
                sx[br][tt][cc] = v;
            }
        }
        __syncwarp();
    }
}

// ---------------------------------------------------------------------------
// Kernel C: tail copy out[:, 16368:16384] = inp[:, 16368:16384]
// ---------------------------------------------------------------------------
__global__ void tail_kernel(const float* __restrict__ inp, float* __restrict__ out) {
    int id = blockIdx.x * blockDim.x + threadIdx.x;   // 1024*16 threads
    if (id >= CHN * 16) return;
    int c = id >> 4;
    int t = NSTEPS + (id & 15);
    out[(size_t)c * TLEN + t] = inp[(size_t)c * TLEN + t];
}

extern "C" void kernel_launch(void* const* d_in, const int* in_sizes, int n_in,
                              void* d_out, int out_size) {
    const float* inp = (const float*)d_in[0];
    float* out = (float*)d_out;
    (void)in_sizes; (void)n_in; (void)out_size;

    colmean_kernel<<<(TP + 255) / 256, 256>>>(inp);
    scan_kernel<<<NCHUNK * 32, 32>>>(inp, out);
    tail_kernel<<<(CHN * 16 + 255) / 256, 256>>>(inp, out);
}

// round 4
// speedup vs baseline: 9.0497x; 1.3858x over previous
#include <cuda_runtime.h>

// harmolearn: 1024-channel LIF scan over 16368 steps, parallel-in-time via
// contraction warm-up chunks (w decays x0.5/step, mem x0.95/step).
//
// Identity: mean(B,axis=0)[j] at step t == colmean[t+j], so
// B_ram[c](t) = 16-window sliding sum of p[c,k] = x_pad[c,k]*colmean[k].

#define CHN    1024
#define TLEN   16384
#define PADW   8
#define TP     (TLEN + 2 * PADW)   // 16400
#define NSTEPS (TLEN - 16)         // 16368
#define NCHUNK 33
#define BODY   496                 // 31 tiles;  33*496 = 16368
#define WARM   512                 // 32 tiles (clamped at t=0 for early chunks)
#define BTILES (BODY / 16)         // 31

__device__ __align__(16) float g_cm2[TP + 16];   // 0.5 * column mean (exact)

// ---------------------------------------------------------------------------
// Kernel A: per-column channel mean * 0.5, strict ascending-c ADD order
// (bit-exact vs reference). Loads batched 32-deep for MLP.
// ---------------------------------------------------------------------------
__global__ void __launch_bounds__(128) colmean_kernel(const float* __restrict__ inp) {
    int tp = blockIdx.x * 128 + threadIdx.x;
    if (tp >= TP) return;
    float m = 0.0f;
    if (tp >= PADW && tp < TLEN + PADW) {
        const float* col = inp + (tp - PADW);
        float s = 0.0f;
        for (int cb = 0; cb < CHN; cb += 32) {
            float v[32];
#pragma unroll
            for (int j = 0; j < 32; ++j)
                v[j] = __ldg(col + (size_t)(cb + j) * TLEN);
#pragma unroll
            for (int j = 0; j < 32; ++j)
                s = __fadd_rn(s, v[j]);            // strict sequential order
        }
        m = (s * (1.0f / CHN)) * 0.5f;             // both scalings exact
    }
    g_cm2[tp] = m;
}

// ---------------------------------------------------------------------------
// Kernel B: chunked scan. One warp per block = 32 consecutive channels x one
// time-chunk. All staging vectorized to .128 ops.
// ---------------------------------------------------------------------------
__global__ void __launch_bounds__(32) scan_kernel(const float* __restrict__ inp,
                                                  float* __restrict__ out) {
    __shared__ float sx[3][32][20];   // x tiles: [buf][channel][t(16)+pad]
    __shared__ float sb[32][20];      // spikes:  [channel][t(16)+pad]

    const int chunk = blockIdx.x >> 5;
    const int c0    = (blockIdx.x & 31) << 5;
    const int lane  = threadIdx.x;
    const float* row = inp + (size_t)(c0 + lane) * TLEN;

    const int tb = chunk * BODY;                 // body start
    int tw = tb - WARM;                          // warm-up start, clamped
    if (tw < 0) tw = 0;                          // early chunks: exact init state
    const int wt        = (tb - tw) >> 4;        // warm tiles actually run
    const int nt        = BTILES + wt;
    const int storeFrom = wt;

    const int cg = lane >> 2;        // channel sub-index for vector staging
    const int tq = lane & 3;         // float4 slot along t

    float w = 1.0f, mem = 0.0f, r = 0.0f;

    // ---- prologue: register windows for tiles 0,1 (scalar, one-time) ----
    float xa[16], pa[16], xb[16], pb[16];
#pragma unroll
    for (int j = 0; j < 16; ++j) {
        int k0 = tw + j;
        float x0 = (k0 >= PADW) ? __ldg(row + (k0 - PADW)) : 0.0f;
        xa[j] = x0;
        pa[j] = x0 * __ldg(&g_cm2[k0]);
        int k1 = tw + 16 + j;                                   // >= 16 > PADW
        float x1 = __ldg(row + (k1 - PADW));
        xb[j] = x1;
        pb[j] = x1 * __ldg(&g_cm2[k1]);
    }

    // ---- prefill smem buffers 0,1: pad ranges [tw+32,tw+48), [tw+48,tw+64) ----
#pragma unroll
    for (int b = 0; b < 2; ++b) {
        int gb = tw + 24 + 16 * b;                 // inp index base (≡8 mod 16)
#pragma unroll
        for (int g = 0; g < 4; ++g) {
            int cc  = cg + 8 * g;
            int idx = gb + 4 * tq;
            float4 v = make_float4(0.f, 0.f, 0.f, 0.f);
            if (idx < TLEN)
                v = *reinterpret_cast<const float4*>(inp + (size_t)(c0 + cc) * TLEN + idx);
            *reinterpret_cast<float4*>(&sx[b][cc][4 * tq]) = v;
        }
    }
    __syncwarp();

    // ---- main loop over 16-step tiles ----
    for (int k = 0; k < nt; ++k) {
        // suffix sums of pa (right-associated)
        float suf[16];
        suf[15] = pa[15];
#pragma unroll
        for (int i = 14; i >= 0; --i) suf[i] = __fadd_rn(pa[i], suf[i + 1]);

        float pre = 0.0f;
        float4 sv;
#pragma unroll
        for (int i = 0; i < 16; ++i) {
            float d05 = (i == 0) ? suf[0] : __fadd_rn(suf[i], pre);   // = 0.5*dot
            w = fminf(fmaxf(__fmaf_rn(0.5f, w, d05), -1.0f), 3.0f);
            float bm = __fmul_rn(0.95f, mem);
            float wx = __fmul_rn(w, xa[i]);
            mem = __fsub_rn(__fadd_rn(bm, wx), r);
            r = (mem > 1.0f) ? 1.0f : 0.0f;
            ((float*)&sv)[i & 3] = r;
            if ((i & 3) == 3)
                *reinterpret_cast<float4*>(&sb[lane][i - 3]) = sv;
            pre = __fadd_rn(pre, pb[i]);
        }
        __syncwarp();

        // flush spikes (.128 along t)
        if (k >= storeFrom) {
            int t0 = tw + 16 * k;
#pragma unroll
            for (int g = 0; g < 4; ++g) {
                int cc = cg + 8 * g;
                float4 v = *reinterpret_cast<const float4*>(&sb[cc][4 * tq]);
                *reinterpret_cast<float4*>(out + (size_t)(c0 + cc) * TLEN + t0 + 4 * tq) = v;
            }
        }

        if (k < nt - 1) {
            // rotate register windows
#pragma unroll
            for (int j = 0; j < 16; ++j) { xa[j] = xb[j]; pa[j] = pb[j]; }

            // consume staged x (buffer k%3) -> new xb/pb for pad [16(k+2),16(k+3))
            int bc = k % 3;
            int t1 = tw + 16 * k + 32;
            float4 cm4[4];
#pragma unroll
            for (int q = 0; q < 4; ++q)
                cm4[q] = *reinterpret_cast<const float4*>(&g_cm2[t1 + 4 * q]);
#pragma unroll
            for (int q = 0; q < 4; ++q) {
                float4 xv = *reinterpret_cast<const float4*>(&sx[bc][lane][4 * q]);
                xb[4 * q + 0] = xv.x;  pb[4 * q + 0] = xv.x * cm4[q].x;
                xb[4 * q + 1] = xv.y;  pb[4 * q + 1] = xv.y * cm4[q].y;
                xb[4 * q + 2] = xv.z;  pb[4 * q + 2] = xv.z * cm4[q].z;
                xb[4 * q + 3] = xv.w;  pb[4 * q + 3] = xv.w * cm4[q].w;
            }

            // refill buffer (k+2)%3 with pad [16(k+4),16(k+5)) -> inp base tw+16k+56
            int br = (k + 2) % 3;
            int gb = tw + 16 * k + 56;
#pragma unroll
            for (int g = 0; g < 4; ++g) {
                int cc  = cg + 8 * g;
                int idx = gb + 4 * tq;
                float4 v = make_float4(0.f, 0.f, 0.f, 0.f);
                if (idx < TLEN)
                    v = *reinterpret_cast<const float4*>(inp + (size_t)(c0 + cc) * TLEN + idx);
                *reinterpret_cast<float4*>(&sx[br][cc][4 * tq]) = v;
            }
        }
        __syncwarp();
    }
}

// ---------------------------------------------------------------------------
// Kernel C: tail copy out[:, 16368:16384] = inp[:, 16368:16384]
// ---------------------------------------------------------------------------
__global__ void tail_kernel(const float* __restrict__ inp, float* __restrict__ out) {
    int id = blockIdx.x * blockDim.x + threadIdx.x;   // 1024*4 threads (float4)
    if (id >= CHN * 4) return;
    int c = id >> 2;
    int t = NSTEPS + 4 * (id & 3);
    *reinterpret_cast<float4*>(out + (size_t)c * TLEN + t) =
        *reinterpret_cast<const float4*>(inp + (size_t)c * TLEN + t);
}

extern "C" void kernel_launch(void* const* d_in, const int* in_sizes, int n_in,
                              void* d_out, int out_size) {
    const float* inp = (const float*)d_in[0];
    float* out = (float*)d_out;
    (void)in_sizes; (void)n_in; (void)out_size;

    colmean_kernel<<<(TP + 127) / 128, 128>>>(inp);
    scan_kernel<<<NCHUNK * 32, 32>>>(inp, out);
    tail_kernel<<<(CHN * 4 + 127) / 128, 128>>>(inp, out);
}

// round 5
// speedup vs baseline: 13.6550x; 1.5089x over previous
#include <cuda_runtime.h>

// harmolearn: 1024-channel LIF scan over 16368 steps, parallel-in-time via
// contraction warm-up chunks (w decays x0.5/step, mem x0.95/step).
// Identity: mean(B,axis=0)[j] at step t == colmean[t+j], so
// B_ram[c](t) = 16-window sliding sum of p[c,k] = x_pad[c,k]*colmean[k].

#define CHN    1024
#define TLEN   16384
#define PADW   8
#define TP     (TLEN + 2 * PADW)   // 16400
#define NSTEPS (TLEN - 16)         // 16368
#define NCHUNK 33
#define BODY   496                 // 31 tiles;  33*496 = 16368
#define WARM   512                 // 32 tiles (clamped at t=0 for early chunks)
#define BTILES (BODY / 16)         // 31

__device__ __align__(16) float g_cm2[TP + 16];   // 0.5 * column mean (exact)

// ---- cp.async helpers -------------------------------------------------------
__device__ __forceinline__ unsigned smem_u32(const void* p) {
    return (unsigned)__cvta_generic_to_shared(p);
}
__device__ __forceinline__ void cp_async16(unsigned dst, const void* src, int src_sz) {
    asm volatile("cp.async.cg.shared.global [%0], [%1], 16, %2;"
                 :: "r"(dst), "l"(src), "r"(src_sz));
}
__device__ __forceinline__ void cp_commit() {
    asm volatile("cp.async.commit_group;");
}
__device__ __forceinline__ void cp_wait1() {
    asm volatile("cp.async.wait_group 1;" ::: "memory");
}

// ---------------------------------------------------------------------------
// Kernel A: per-column channel mean * 0.5, strict ascending-c ADD order
// (bit-exact vs reference). 4-deep software pipeline over 16-element batches:
// loads run ~4 batches ahead of the (order-preserving) serial add chain.
// ---------------------------------------------------------------------------
__global__ void __launch_bounds__(64) colmean_kernel(const float* __restrict__ inp) {
    int tp = blockIdx.x * 64 + threadIdx.x;
    if (tp >= TP) return;
    float m = 0.0f;
    if (tp >= PADW && tp < TLEN + PADW) {
        const float* col = inp + (tp - PADW);
        float buf[4][16];
#pragma unroll
        for (int d = 0; d < 4; ++d)
#pragma unroll
            for (int j = 0; j < 16; ++j)
                buf[d][j] = __ldg(col + (size_t)(16 * d + j) * TLEN);

        float s = 0.0f;
#pragma unroll 4
        for (int cb = 0; cb < CHN; cb += 16) {
            const int d = (cb >> 4) & 3;
#pragma unroll
            for (int j = 0; j < 16; ++j)
                s = __fadd_rn(s, buf[d][j]);          // strict ascending order
            const int nx = cb + 64;
            if (nx < CHN) {
#pragma unroll
                for (int j = 0; j < 16; ++j)
                    buf[d][j] = __ldg(col + (size_t)(nx + j) * TLEN);
            }
        }
        m = (s * (1.0f / CHN)) * 0.5f;                // both scalings exact
    }
    g_cm2[tp] = m;
}

// ---------------------------------------------------------------------------
// Kernel B: chunked scan. One warp per block = 32 consecutive channels x one
// time-chunk. x staged through smem via cp.async issued 2 tiles ahead.
// ---------------------------------------------------------------------------
__global__ void __launch_bounds__(32) scan_kernel(const float* __restrict__ inp,
                                                  float* __restrict__ out) {
    __shared__ __align__(16) float sx[3][32][20];   // x tiles [buf][ch][t16+pad]
    __shared__ __align__(16) float sb[32][20];      // spikes  [ch][t16+pad]

    const int chunk = blockIdx.x >> 5;
    const int c0    = (blockIdx.x & 31) << 5;
    const int lane  = threadIdx.x;
    const float* row = inp + (size_t)(c0 + lane) * TLEN;

    const int tb = chunk * BODY;
    int tw = tb - WARM;
    if (tw < 0) tw = 0;                          // early chunks: exact init state
    const int wt        = (tb - tw) >> 4;
    const int nt        = BTILES + wt;
    const int storeFrom = wt;

    const int cg = lane >> 2;        // channel sub-index for vector staging
    const int tq = lane & 3;         // float4 slot along t

    // tail copy folded into last chunk: out[:,16368:16384] = inp[:,16368:16384]
    if (chunk == NCHUNK - 1) {
#pragma unroll
        for (int q = 0; q < 4; ++q) {
            float4 v = *reinterpret_cast<const float4*>(row + NSTEPS + 4 * q);
            *reinterpret_cast<float4*>(out + (size_t)(c0 + lane) * TLEN + NSTEPS + 4 * q) = v;
        }
    }

    float w = 1.0f, mem = 0.0f, r = 0.0f;

    // ---- prologue: register windows for tiles 0,1 (scalar, one-time) ----
    float xa[16], pa[16], xb[16], pb[16];
#pragma unroll
    for (int j = 0; j < 16; ++j) {
        int k0 = tw + j;
        float x0 = (k0 >= PADW) ? __ldg(row + (k0 - PADW)) : 0.0f;
        xa[j] = x0;
        pa[j] = x0 * __ldg(&g_cm2[k0]);
        int k1 = tw + 16 + j;
        float x1 = __ldg(row + (k1 - PADW));
        xb[j] = x1;
        pb[j] = x1 * __ldg(&g_cm2[k1]);
    }

    // ---- prefill smem buffers 0,1 via cp.async (groups "-2","-1") ----
    // buffer consumed at tile k holds pad [tw+16k+32,+48) -> inp base tw+16k+24
#pragma unroll
    for (int b = 0; b < 2; ++b) {
        int gb = tw + 24 + 16 * b;
#pragma unroll
        for (int g = 0; g < 4; ++g) {
            int cc  = cg + 8 * g;
            int idx = gb + 4 * tq;
            int ok  = (idx < TLEN);
            const float* src = inp + (size_t)(c0 + cc) * TLEN + (ok ? idx : 0);
            cp_async16(smem_u32(&sx[b][cc][4 * tq]), src, ok ? 16 : 0);
        }
        cp_commit();
    }

    // ---- main loop over 16-step tiles ----
    for (int k = 0; k < nt; ++k) {
        // suffix sums of pa (right-associated)
        float suf[16];
        suf[15] = pa[15];
#pragma unroll
        for (int i = 14; i >= 0; --i) suf[i] = __fadd_rn(pa[i], suf[i + 1]);

        float pre = 0.0f;
        float4 sv;
#pragma unroll
        for (int i = 0; i < 16; ++i) {
            float d05 = (i == 0) ? suf[0] : __fadd_rn(suf[i], pre);   // = 0.5*dot
            w = fminf(fmaxf(__fmaf_rn(0.5f, w, d05), -1.0f), 3.0f);
            float bm = __fmul_rn(0.95f, mem);
            float wx = __fmul_rn(w, xa[i]);
            mem = __fsub_rn(__fadd_rn(bm, wx), r);
            r = (mem > 1.0f) ? 1.0f : 0.0f;
            ((float*)&sv)[i & 3] = r;
            if ((i & 3) == 3)
                *reinterpret_cast<float4*>(&sb[lane][i - 3]) = sv;
            pre = __fadd_rn(pre, pb[i]);
        }
        __syncwarp();

        // flush spikes (.128 along t)
        if (k >= storeFrom) {
            int t0 = tw + 16 * k;
#pragma unroll
            for (int g = 0; g < 4; ++g) {
                int cc = cg + 8 * g;
                float4 v = *reinterpret_cast<const float4*>(&sb[cc][4 * tq]);
                *reinterpret_cast<float4*>(out + (size_t)(c0 + cc) * TLEN + t0 + 4 * tq) = v;
            }
        }

        if (k < nt - 1) {
            // rotate register windows
#pragma unroll
            for (int j = 0; j < 16; ++j) { xa[j] = xb[j]; pa[j] = pb[j]; }

            // wait for group issued at tile k-2 (fills buffer k%3), then consume
            cp_wait1();
            __syncwarp();

            int bc = k % 3;
            int t1 = tw + 16 * k + 32;
            float4 cm4[4];
#pragma unroll
            for (int q = 0; q < 4; ++q)
                cm4[q] = *reinterpret_cast<const float4*>(&g_cm2[t1 + 4 * q]);
#pragma unroll
            for (int q = 0; q < 4; ++q) {
                float4 xv = *reinterpret_cast<const float4*>(&sx[bc][lane][4 * q]);
                xb[4 * q + 0] = xv.x;  pb[4 * q + 0] = xv.x * cm4[q].x;
                xb[4 * q + 1] = xv.y;  pb[4 * q + 1] = xv.y * cm4[q].y;
                xb[4 * q + 2] = xv.z;  pb[4 * q + 2] = xv.z * cm4[q].z;
                xb[4 * q + 3] = xv.w;  pb[4 * q + 3] = xv.w * cm4[q].w;
            }

            // issue group k: fill buffer (k+2)%3 with pad [16(k+4),+16) data,
            // inp base tw+16k+56; consumed at tile k+2.
            int br = (k + 2) % 3;
            int gb = tw + 16 * k + 56;
#pragma unroll
            for (int g = 0; g < 4; ++g) {
                int cc  = cg + 8 * g;
                int idx = gb + 4 * tq;
                int ok  = (idx < TLEN);
                const float* src = inp + (size_t)(c0 + cc) * TLEN + (ok ? idx : 0);
                cp_async16(smem_u32(&sx[br][cc][4 * tq]), src, ok ? 16 : 0);
            }
            cp_commit();
        }
        __syncwarp();
    }
}

extern "C" void kernel_launch(void* const* d_in, const int* in_sizes, int n_in,
                              void* d_out, int out_size) {
    const float* inp = (const float*)d_in[0];
    float* out = (float*)d_out;
    (void)in_sizes; (void)n_in; (void)out_size;

    colmean_kernel<<<(TP + 63) / 64, 64>>>(inp);
    scan_kernel<<<NCHUNK * 32, 32>>>(inp, out);
}

// round 7
// speedup vs baseline: 16.8370x; 1.2330x over previous
#include <cuda_runtime.h>

// harmolearn: 1024-channel LIF scan over 16368 steps, parallel-in-time via
// contraction warm-up chunks (w decays x0.5/step, mem x0.95/step).
// Identity: mean(B,axis=0)[j] at step t == colmean[t+j], so
// B_ram[c](t) = 16-window sliding sum of p[c,k] = x_pad[c,k]*colmean[k].

#define CHN    1024
#define TLEN   16384
#define PADW   8
#define TP     (TLEN + 2 * PADW)   // 16400
#define NSTEPS (TLEN - 16)         // 16368
#define NCHUNK 33
#define BODY   496                 // 31 tiles;  33*496 = 16368
#define WARM   512                 // 32 tiles (clamped at t=0 for early chunks)
#define BTILES (BODY / 16)         // 31

// padded past TP so speculative cp.async prefetches stay in-bounds
__device__ __align__(16) float g_cm2[TP + 64];

// ---- cp.async helpers -------------------------------------------------------
__device__ __forceinline__ unsigned smem_u32(const void* p) {
    return (unsigned)__cvta_generic_to_shared(p);
}
__device__ __forceinline__ void cp_async16(unsigned dst, const void* src, int src_sz) {
    asm volatile("cp.async.cg.shared.global [%0], [%1], 16, %2;"
                 :: "r"(dst), "l"(src), "r"(src_sz));
}
__device__ __forceinline__ void cp_commit() {
    asm volatile("cp.async.commit_group;");
}
__device__ __forceinline__ void cp_wait1() {
    asm volatile("cp.async.wait_group 1;" ::: "memory");
}
__device__ __forceinline__ void cp_wait3() {
    asm volatile("cp.async.wait_group 3;" ::: "memory");
}
__device__ __forceinline__ void cp_wait0() {
    asm volatile("cp.async.wait_group 0;" ::: "memory");
}

// ---------------------------------------------------------------------------
// Kernel A: per-column channel mean * 0.5, strict ascending-c ADD order
// (bit-exact vs reference). Rows staged through a 5-deep cp.async smem ring.
// Block = 128 columns; stage = 16 rows x 128 cols = 8KB.
// ---------------------------------------------------------------------------
#define CM_DEPTH 5
__global__ void __launch_bounds__(128) colmean_kernel(const float* __restrict__ inp) {
    __shared__ __align__(16) float tile[CM_DEPTH][16][128];

    const int  tid  = threadIdx.x;
    const long cb   = (long)blockIdx.x * 128 - PADW;   // inp col of smem col 0
    const int  rr   = tid >> 5;                        // row sub-index 0..3
    const int  ccol = 4 * (tid & 31);                  // smem col group

    const long col  = cb + ccol;
    int szb = (col < 0) ? 0 : (int)((long)TLEN - col) * 4;
    szb = szb < 0 ? 0 : (szb > 16 ? 16 : szb);
    const float* srcBase = (szb > 0) ? (inp + col) : inp;

    // prefill stages 0..3
#pragma unroll
    for (int s = 0; s < CM_DEPTH - 1; ++s) {
#pragma unroll
        for (int q = 0; q < 4; ++q) {
            int row = 16 * s + rr + 4 * q;
            cp_async16(smem_u32(&tile[s][rr + 4 * q][ccol]),
                       srcBase + (size_t)row * TLEN, szb);
        }
        cp_commit();
    }

    const int tp      = blockIdx.x * 128 + tid;
    const bool active = (tp >= PADW) && (tp < TLEN + PADW);
    float s_acc = 0.0f;

    for (int s = 0; s < CHN / 16; ++s) {               // 64 stages
        cp_wait3();
        __syncthreads();
        if (s + CM_DEPTH - 1 < CHN / 16) {
            int sb = (s + CM_DEPTH - 1) % CM_DEPTH;
#pragma unroll
            for (int q = 0; q < 4; ++q) {
                int row = 16 * (s + CM_DEPTH - 1) + rr + 4 * q;
                cp_async16(smem_u32(&tile[sb][rr + 4 * q][ccol]),
                           srcBase + (size_t)row * TLEN, szb);
            }
            cp_commit();
        } else {
            cp_commit();                               // uniform group counting
        }
        if (active) {
            const int b = s % CM_DEPTH;
#pragma unroll
            for (int rI = 0; rI < 16; ++rI)
                s_acc = __fadd_rn(s_acc, tile[b][rI][tid]);  // strict ascending c
        }
    }
    if (tp < TP)
        g_cm2[tp] = active ? (s_acc * (1.0f / CHN)) * 0.5f : 0.0f;
}

// ---------------------------------------------------------------------------
// Kernel B: chunked scan. One warp per block = 32 consecutive channels x one
// time-chunk. x AND cm staged via cp.async two tiles ahead; pair-unrolled
// tiles; pointer-increment addressing; spike flush batched per pair.
// Even-nt chunks (chunk 1) run one standalone tile + role swap first.
// ---------------------------------------------------------------------------

#define STEPS(PA_, XA_, PB_, SB_)                                         \
  {                                                                       \
    float suf[16];                                                        \
    suf[15] = PA_[15];                                                    \
    _Pragma("unroll")                                                     \
    for (int i = 14; i >= 0; --i) suf[i] = __fadd_rn(PA_[i], suf[i + 1]); \
    float pre = 0.0f;                                                     \
    float4 sv;                                                            \
    _Pragma("unroll")                                                     \
    for (int i = 0; i < 16; ++i) {                                        \
      float d05 = (i == 0) ? suf[0] : __fadd_rn(suf[i], pre);             \
      w = fminf(fmaxf(__fmaf_rn(0.5f, w, d05), -1.0f), 3.0f);             \
      float bm = __fmul_rn(0.95f, mem);                                   \
      float wx = __fmul_rn(w, XA_[i]);                                    \
      mem = __fsub_rn(__fadd_rn(bm, wx), r);                              \
      r = (mem > 1.0f) ? 1.0f : 0.0f;                                     \
      ((float*)&sv)[i & 3] = r;                                           \
      if ((i & 3) == 3)                                                   \
        *reinterpret_cast<float4*>(&SB_[lane][i - 3]) = sv;               \
      pre = __fadd_rn(pre, PB_[i]);                                       \
    }                                                                     \
  }

#define CONSUME(XD_, PD_, BUF_)                                             \
  {                                                                         \
    const int bb_ = (BUF_);                                                 \
    float4 cm4[4];                                                          \
    _Pragma("unroll")                                                       \
    for (int q = 0; q < 4; ++q)                                             \
      cm4[q] = *reinterpret_cast<const float4*>(&cmx[bb_][4 * q]);          \
    _Pragma("unroll")                                                       \
    for (int q = 0; q < 4; ++q) {                                           \
      float4 xv = *reinterpret_cast<const float4*>(&sx[bb_][lane][4 * q]);  \
      XD_[4*q+0] = xv.x;  PD_[4*q+0] = __fmul_rn(xv.x, cm4[q].x);           \
      XD_[4*q+1] = xv.y;  PD_[4*q+1] = __fmul_rn(xv.y, cm4[q].y);           \
      XD_[4*q+2] = xv.z;  PD_[4*q+2] = __fmul_rn(xv.z, cm4[q].z);           \
      XD_[4*q+3] = xv.w;  PD_[4*q+3] = __fmul_rn(xv.w, cm4[q].w);           \
    }                                                                       \
  }

#define ISSUE(OFF_, BUF_)                                                   \
  {                                                                         \
    const int bb_ = (BUF_);                                                 \
    int szb_ = (TLEN - (idx + (OFF_))) * 4;                                 \
    szb_ = szb_ < 0 ? 0 : (szb_ > 16 ? 16 : szb_);                          \
    _Pragma("unroll")                                                       \
    for (int g = 0; g < 4; ++g) {                                           \
      const float* sp_ = szb_ ? (pSrc[g] + (OFF_)) : inp;                   \
      cp_async16(smem_u32(&sx[bb_][cg + 8 * g][4 * tq]), sp_, szb_);        \
    }                                                                       \
    if (lane < 4)                                                           \
      cp_async16(smem_u32(&cmx[bb_][4 * laneq]), pCm + (OFF_), 16);         \
    cp_commit();                                                            \
  }

#define FLUSH(SB_, OFF_)                                                     \
    _Pragma("unroll")                                                        \
    for (int g = 0; g < 4; ++g) {                                            \
      float4 v_ = *reinterpret_cast<const float4*>(&SB_[cg + 8 * g][4 * tq]);\
      *reinterpret_cast<float4*>(pOut[g] + (OFF_)) = v_;                     \
    }

__global__ void __launch_bounds__(32) scan_kernel(const float* __restrict__ inp,
                                                  float* __restrict__ out) {
    __shared__ __align__(16) float sx[4][32][20];   // x tiles ring
    __shared__ __align__(16) float cmx[4][16];      // cm tiles ring
    __shared__ __align__(16) float sb0[32][20];     // spikes (even-role tile)
    __shared__ __align__(16) float sb1[32][20];     // spikes (odd-role tile)

    const int chunk = blockIdx.x >> 5;
    const int c0    = (blockIdx.x & 31) << 5;
    const int lane  = threadIdx.x;
    const float* row = inp + (size_t)(c0 + lane) * TLEN;

    const int tb = chunk * BODY;
    int tw = tb - WARM;
    if (tw < 0) tw = 0;                              // exact init state if clamped
    const int wt        = (tb - tw) >> 4;
    const int nt        = BTILES + wt;               // 31, 62 (chunk 1), or 63
    const int storeFrom = wt;

    const int cg    = lane >> 2;
    const int tq    = lane & 3;
    const int laneq = lane & 3;

    // tail copy folded into last chunk
    if (chunk == NCHUNK - 1) {
#pragma unroll
        for (int q = 0; q < 4; ++q) {
            float4 v = *reinterpret_cast<const float4*>(row + NSTEPS + 4 * q);
            *reinterpret_cast<float4*>(out + (size_t)(c0 + lane) * TLEN + NSTEPS + 4 * q) = v;
        }
    }

    float w = 1.0f, mem = 0.0f, r = 0.0f;

    // ---- prologue: register windows 0 and 1 (scalar, one-time) ----
    float XA[16], PA[16], XB[16], PB[16];
#pragma unroll
    for (int j = 0; j < 16; ++j) {
        int k0 = tw + j;
        float x0 = (k0 >= PADW) ? __ldg(row + (k0 - PADW)) : 0.0f;
        XA[j] = x0;
        PA[j] = __fmul_rn(x0, __ldg(&g_cm2[k0]));
        int k1 = tw + 16 + j;
        float x1 = __ldg(row + (k1 - PADW));
        XB[j] = x1;
        PB[j] = __fmul_rn(x1, __ldg(&g_cm2[k1]));
    }

    // ---- prefill groups for windows 2 and 3 (buffers 0,1) ----
#pragma unroll
    for (int b = 0; b < 2; ++b) {
        int gb = tw + 24 + 16 * b;
#pragma unroll
        for (int g = 0; g < 4; ++g)
            cp_async16(smem_u32(&sx[b][cg + 8 * g][4 * tq]),
                       inp + (size_t)(c0 + cg + 8 * g) * TLEN + gb + 4 * tq, 16);
        if (lane < 4)
            cp_async16(smem_u32(&cmx[b][4 * laneq]), &g_cm2[tw + 32 + 16 * b + 4 * laneq], 16);
        cp_commit();
    }

    // ---- incrementing pointers (point at window k+4 data for tile k) ----
    const float* pSrc[4];
    float*       pOut[4];
#pragma unroll
    for (int g = 0; g < 4; ++g) {
        pSrc[g] = inp + (size_t)(c0 + cg + 8 * g) * TLEN + tw + 56 + 4 * tq;
        pOut[g] = out + (size_t)(c0 + cg + 8 * g) * TLEN + tw + 4 * tq;
    }
    const float* pCm = g_cm2 + tw + 64 + 4 * laneq;
    int idx = tw + 56 + 4 * tq;

    // ---- even-nt fixup: standalone tile 0 then role swap (chunk 1 only) ----
    int kbase = 0;
    if ((nt & 1) == 0) {
        STEPS(PA, XA, PB, sb0);
        cp_wait1();
        __syncwarp();
        CONSUME(XA, PA, 0);              // window 2 -> XA/PA
        ISSUE(0, 2);                     // window 4 -> buffer 2
        if (0 >= storeFrom) { FLUSH(sb0, 0); }
#pragma unroll
        for (int g = 0; g < 4; ++g) { pSrc[g] += 16; pOut[g] += 16; }
        pCm += 16;
        idx += 16;
#pragma unroll
        for (int j = 0; j < 16; ++j) {   // swap roles: next tile uses PA=window1
            float t0 = PA[j]; PA[j] = PB[j]; PB[j] = t0;
            float t1 = XA[j]; XA[j] = XB[j]; XB[j] = t1;
        }
        kbase = 1;
        __syncwarp();
    }

    // ---- pair-unrolled main loop ----
    const int pairs = (nt - kbase - 1) >> 1;
    for (int m = 0; m < pairs; ++m) {
        const int k = kbase + 2 * m;

        // tile k: pa=PA, x=XA, pb=PB
        STEPS(PA, XA, PB, sb0);
        cp_wait1();
        __syncwarp();
        CONSUME(XA, PA, k & 3);          // window k+2
        ISSUE(0, (k + 2) & 3);           // window k+4

        // tile k+1: pa=PB, x=XB, pb=PA(new)
        STEPS(PB, XB, PA, sb1);
        cp_wait1();
        __syncwarp();
        CONSUME(XB, PB, (k + 1) & 3);    // window k+3
        ISSUE(16, (k + 3) & 3);          // window k+5

        if (k >= storeFrom) {
            FLUSH(sb0, 0);
            FLUSH(sb1, 16);
        }

#pragma unroll
        for (int g = 0; g < 4; ++g) { pSrc[g] += 32; pOut[g] += 32; }
        pCm += 32;
        idx += 32;
        __syncwarp();                    // protect sb0/sb1 reuse next pair
    }

    // ---- epilogue: last tile (nt-1, role A after even # of flips) ----
    STEPS(PA, XA, PB, sb0);
    __syncwarp();
    FLUSH(sb0, 0);
    cp_wait0();
}

extern "C" void kernel_launch(void* const* d_in, const int* in_sizes, int n_in,
                              void* d_out, int out_size) {
    const float* inp = (const float*)d_in[0];
    float* out = (float*)d_out;
    (void)in_sizes; (void)n_in; (void)out_size;

    colmean_kernel<<<(TP + 127) / 128, 128>>>(inp);
    scan_kernel<<<NCHUNK * 32, 32>>>(inp, out);
}